// round 1
// baseline (speedup 1.0000x reference)
#include <cuda_runtime.h>
#include <cuda_bf16.h>
#include <cstdint>

// Problem constants
#define BB   2
#define TT   2048
#define CC   1024
#define NH   16
#define HD   64
#define BT   (BB*TT)          // 4096
#define C3   (3*CC)           // 3072
#define SCALE 0.125f          // 1/sqrt(64)

// Scratch (device globals: allocation-free rule)
__device__ float g_qkv[(size_t)BT * C3];   // [4096, 3072]
__device__ float g_y[(size_t)BT * CC];     // [4096, 1024]

// ---------------------------------------------------------------------------
// SGEMM: C[M,N] = A[M,K] @ B[K,N] + bias[N]   (all row-major fp32)
// 128x128 block tile, BK=16, 256 threads, 8x8 per-thread microtile
// ---------------------------------------------------------------------------
#define BM 128
#define BN 128
#define BK 16

__global__ __launch_bounds__(256) void sgemm_bias(
    const float* __restrict__ A, const float* __restrict__ Bm,
    const float* __restrict__ bias, float* __restrict__ Cm,
    int M, int N, int K)
{
    __shared__ float As[BK][BM];
    __shared__ float Bs[BK][BN];

    const int tid = threadIdx.x;
    const int tx = tid & 15;        // 0..15 -> n
    const int ty = tid >> 4;        // 0..15 -> m
    const int m0 = blockIdx.y * BM;
    const int n0 = blockIdx.x * BN;

    float acc[8][8];
#pragma unroll
    for (int i = 0; i < 8; i++)
#pragma unroll
        for (int j = 0; j < 8; j++) acc[i][j] = 0.f;

    for (int k0 = 0; k0 < K; k0 += BK) {
        // Load A tile: 128 rows x 16 cols, store transposed As[k][m]
#pragma unroll
        for (int i = 0; i < 2; i++) {
            int idx = tid + i * 256;          // 0..511
            int row = idx >> 2;               // 0..127
            int c4  = idx & 3;                // 0..3
            float4 av = *(const float4*)(A + (size_t)(m0 + row) * K + k0 + c4 * 4);
            As[c4 * 4 + 0][row] = av.x;
            As[c4 * 4 + 1][row] = av.y;
            As[c4 * 4 + 2][row] = av.z;
            As[c4 * 4 + 3][row] = av.w;
        }
        // Load B tile: 16 rows x 128 cols
#pragma unroll
        for (int i = 0; i < 2; i++) {
            int idx = tid + i * 256;
            int row = idx >> 5;               // 0..15
            int c4  = idx & 31;               // 0..31
            *(float4*)(&Bs[row][c4 * 4]) =
                *(const float4*)(Bm + (size_t)(k0 + row) * N + n0 + c4 * 4);
        }
        __syncthreads();

#pragma unroll
        for (int kk = 0; kk < BK; kk++) {
            float a[8], b[8];
            *(float4*)(a)     = *(const float4*)(&As[kk][ty * 8]);
            *(float4*)(a + 4) = *(const float4*)(&As[kk][ty * 8 + 4]);
            *(float4*)(b)     = *(const float4*)(&Bs[kk][tx * 8]);
            *(float4*)(b + 4) = *(const float4*)(&Bs[kk][tx * 8 + 4]);
#pragma unroll
            for (int i = 0; i < 8; i++)
#pragma unroll
                for (int j = 0; j < 8; j++)
                    acc[i][j] = fmaf(a[i], b[j], acc[i][j]);
        }
        __syncthreads();
    }

    // Epilogue: +bias, store
#pragma unroll
    for (int i = 0; i < 8; i++) {
        int m = m0 + ty * 8 + i;
#pragma unroll
        for (int j = 0; j < 8; j += 4) {
            int n = n0 + tx * 8 + j;
            float4 v;
            v.x = acc[i][j + 0] + bias[n + 0];
            v.y = acc[i][j + 1] + bias[n + 1];
            v.z = acc[i][j + 2] + bias[n + 2];
            v.w = acc[i][j + 3] + bias[n + 3];
            *(float4*)(Cm + (size_t)m * N + n) = v;
        }
    }
}

// ---------------------------------------------------------------------------
// Flash attention (causal). One block per (q_tile, head, batch).
// Q tile 64 rows, K/V tiles 64 rows, D=64. 256 threads.
// Thread (tx,ty): S fragment rows r=ty*4+i, cols c=tx+16*j (strided to avoid
// 8-way smem conflicts); O fragment rows r=ty*4+i, cols d=tx*4+j.
// P is staged transposed in smem (Ps[c][r]) so PV reads are float4.
// ---------------------------------------------------------------------------
#define AQ 64
#define PADF 68      // floats per smem row (64 + 4), float4-aligned, stride 4 banks

__global__ __launch_bounds__(256) void attn_kernel(const float* __restrict__ qkv,
                                                   float* __restrict__ y)
{
    extern __shared__ float sm[];
    float* Qs = sm;                 // [64][68]
    float* Ks = sm + 64 * PADF;     // [64][68]
    float* Vs = sm + 2 * 64 * PADF; // [64][68]
    float* Ps = sm + 3 * 64 * PADF; // [64][68]  (transposed: Ps[c][r])

    const int tid = threadIdx.x;
    const int tx = tid & 15;
    const int ty = tid >> 4;
    const int qt = blockIdx.x;      // q tile (0..31)
    const int h  = blockIdx.y;      // head
    const int b  = blockIdx.z;      // batch
    const int q0 = qt * AQ;

    // Load Q tile (scaled by 1/sqrt(D))
    {
        const float* qbase = qkv + ((size_t)(b * TT + q0)) * C3 + h * HD;
#pragma unroll
        for (int i = 0; i < 4; i++) {
            int idx = tid + i * 256;     // 0..1023
            int row = idx >> 4;          // 0..63
            int c4  = idx & 15;          // 0..15
            float4 v = *(const float4*)(qbase + (size_t)row * C3 + c4 * 4);
            v.x *= SCALE; v.y *= SCALE; v.z *= SCALE; v.w *= SCALE;
            *(float4*)(&Qs[row * PADF + c4 * 4]) = v;
        }
    }

    float o[4][4];
    float mrow[4], lrow[4];
#pragma unroll
    for (int i = 0; i < 4; i++) {
        mrow[i] = -INFINITY; lrow[i] = 0.f;
#pragma unroll
        for (int j = 0; j < 4; j++) o[i][j] = 0.f;
    }

    for (int kt = 0; kt <= qt; kt++) {
        __syncthreads();   // previous iter's PV reads of Ks/Vs/Ps done

        // Load K,V tiles
        {
            const float* kbase = qkv + ((size_t)(b * TT + kt * AQ)) * C3 + CC + h * HD;
            const float* vbase = kbase + CC;
#pragma unroll
            for (int i = 0; i < 4; i++) {
                int idx = tid + i * 256;
                int row = idx >> 4;
                int c4  = idx & 15;
                *(float4*)(&Ks[row * PADF + c4 * 4]) =
                    *(const float4*)(kbase + (size_t)row * C3 + c4 * 4);
                *(float4*)(&Vs[row * PADF + c4 * 4]) =
                    *(const float4*)(vbase + (size_t)row * C3 + c4 * 4);
            }
        }
        __syncthreads();

        // S = Q K^T  (fragment: rows ty*4+i, cols tx+16*j)
        float s[4][4];
#pragma unroll
        for (int i = 0; i < 4; i++)
#pragma unroll
            for (int j = 0; j < 4; j++) s[i][j] = 0.f;

#pragma unroll
        for (int d4 = 0; d4 < 16; d4++) {
            float4 qv[4], kv[4];
#pragma unroll
            for (int i = 0; i < 4; i++)
                qv[i] = *(const float4*)(&Qs[(ty * 4 + i) * PADF + d4 * 4]);
#pragma unroll
            for (int j = 0; j < 4; j++)
                kv[j] = *(const float4*)(&Ks[(tx + 16 * j) * PADF + d4 * 4]);
#pragma unroll
            for (int i = 0; i < 4; i++)
#pragma unroll
                for (int j = 0; j < 4; j++) {
                    s[i][j] = fmaf(qv[i].x, kv[j].x, s[i][j]);
                    s[i][j] = fmaf(qv[i].y, kv[j].y, s[i][j]);
                    s[i][j] = fmaf(qv[i].z, kv[j].z, s[i][j]);
                    s[i][j] = fmaf(qv[i].w, kv[j].w, s[i][j]);
                }
        }

        // Causal mask on the diagonal tile
        if (kt == qt) {
#pragma unroll
            for (int i = 0; i < 4; i++) {
                int r = ty * 4 + i;
#pragma unroll
                for (int j = 0; j < 4; j++) {
                    int c = tx + 16 * j;
                    if (c > r) s[i][j] = -1e30f;
                }
            }
        }

        // Online softmax (row reductions over the 16 lanes sharing ty)
#pragma unroll
        for (int i = 0; i < 4; i++) {
            float tm = fmaxf(fmaxf(s[i][0], s[i][1]), fmaxf(s[i][2], s[i][3]));
#pragma unroll
            for (int off = 8; off > 0; off >>= 1)
                tm = fmaxf(tm, __shfl_xor_sync(0xffffffffu, tm, off));
            float m_new = fmaxf(mrow[i], tm);
            float alpha = __expf(mrow[i] - m_new);
            mrow[i] = m_new;
            float rs = 0.f;
#pragma unroll
            for (int j = 0; j < 4; j++) {
                s[i][j] = __expf(s[i][j] - m_new);
                rs += s[i][j];
            }
#pragma unroll
            for (int off = 8; off > 0; off >>= 1)
                rs += __shfl_xor_sync(0xffffffffu, rs, off);
            lrow[i] = lrow[i] * alpha + rs;
#pragma unroll
            for (int j = 0; j < 4; j++) o[i][j] *= alpha;
        }

        // Stage P transposed: Ps[c][r]
#pragma unroll
        for (int j = 0; j < 4; j++) {
            float4 v = make_float4(s[0][j], s[1][j], s[2][j], s[3][j]);
            *(float4*)(&Ps[(tx + 16 * j) * PADF + ty * 4]) = v;
        }
        __syncthreads();

        // O += P @ V
#pragma unroll 4
        for (int c = 0; c < 64; c++) {
            float4 pv = *(const float4*)(&Ps[c * PADF + ty * 4]);
            float4 vv = *(const float4*)(&Vs[c * PADF + tx * 4]);
            o[0][0] = fmaf(pv.x, vv.x, o[0][0]); o[0][1] = fmaf(pv.x, vv.y, o[0][1]);
            o[0][2] = fmaf(pv.x, vv.z, o[0][2]); o[0][3] = fmaf(pv.x, vv.w, o[0][3]);
            o[1][0] = fmaf(pv.y, vv.x, o[1][0]); o[1][1] = fmaf(pv.y, vv.y, o[1][1]);
            o[1][2] = fmaf(pv.y, vv.z, o[1][2]); o[1][3] = fmaf(pv.y, vv.w, o[1][3]);
            o[2][0] = fmaf(pv.z, vv.x, o[2][0]); o[2][1] = fmaf(pv.z, vv.y, o[2][1]);
            o[2][2] = fmaf(pv.z, vv.z, o[2][2]); o[2][3] = fmaf(pv.z, vv.w, o[2][3]);
            o[3][0] = fmaf(pv.w, vv.x, o[3][0]); o[3][1] = fmaf(pv.w, vv.y, o[3][1]);
            o[3][2] = fmaf(pv.w, vv.z, o[3][2]); o[3][3] = fmaf(pv.w, vv.w, o[3][3]);
        }
    }

    // Normalize and store y[b, q0+r, h*64 + d]
#pragma unroll
    for (int i = 0; i < 4; i++) {
        float inv = 1.0f / lrow[i];
        int r = q0 + ty * 4 + i;
        float4 v = make_float4(o[i][0] * inv, o[i][1] * inv, o[i][2] * inv, o[i][3] * inv);
        *(float4*)(&y[((size_t)(b * TT + r)) * CC + h * HD + tx * 4]) = v;
    }
}

// ---------------------------------------------------------------------------
// Launch
// ---------------------------------------------------------------------------
extern "C" void kernel_launch(void* const* d_in, const int* in_sizes, int n_in,
                              void* d_out, int out_size)
{
    const float* x      = (const float*)d_in[0];  // [2,2048,1024]
    const float* w_attn = (const float*)d_in[1];  // [1024,3072]
    const float* b_attn = (const float*)d_in[2];  // [3072]
    const float* w_proj = (const float*)d_in[3];  // [1024,1024]
    const float* b_proj = (const float*)d_in[4];  // [1024]
    float* out = (float*)d_out;                   // [2,2048,1024]

    float* qkv; cudaGetSymbolAddress((void**)&qkv, g_qkv);
    float* yb;  cudaGetSymbolAddress((void**)&yb,  g_y);

    const int smem_attn = 4 * 64 * PADF * sizeof(float);   // 69632 B
    cudaFuncSetAttribute(attn_kernel, cudaFuncAttributeMaxDynamicSharedMemorySize,
                         smem_attn);

    // 1) QKV = x @ w_attn + b_attn
    sgemm_bias<<<dim3(C3 / BN, BT / BM), 256>>>(x, w_attn, b_attn, qkv, BT, C3, CC);

    // 2) causal multi-head attention
    attn_kernel<<<dim3(TT / AQ, NH, BB), 256, smem_attn>>>(qkv, yb);

    // 3) out = y @ w_proj + b_proj
    sgemm_bias<<<dim3(CC / BN, BT / BM), 256>>>(yb, w_proj, b_proj, out, BT, CC, CC);
}

// round 4
// speedup vs baseline: 2.8915x; 2.8915x over previous
#include <cuda_runtime.h>
#include <cstdint>
#include <cmath>

// ---------------------------------------------------------------- constants
#define BB   2
#define TT   2048
#define CC   1024
#define NH   16
#define HD   64
#define BT   (BB*TT)          // 4096
#define C3   (3*CC)           // 3072
#define SCALE 0.125f

// ---------------------------------------------------------------- scratch
__device__ float g_qkv[(size_t)BT * C3];   // [4096,3072] (tf32-clean)
__device__ float g_y  [(size_t)BT * CC];   // attention out (tf32-clean)
__device__ float g_xr [(size_t)BT * CC];   // x rounded to tf32
__device__ float g_wa [(size_t)CC * C3];   // w_attn rounded to tf32
__device__ float g_wp [(size_t)CC * CC];   // w_proj rounded to tf32

// ---------------------------------------------------------------- utils
__device__ __forceinline__ uint32_t smem_u32(const void* p) {
    uint32_t a;
    asm("{ .reg .u64 t; cvta.to.shared.u64 t, %1; cvt.u32.u64 %0, t; }" : "=r"(a) : "l"(p));
    return a;
}
__device__ __forceinline__ float rn_tf32(float x) {
    uint32_t r;
    asm("cvt.rna.tf32.f32 %0, %1;" : "=r"(r) : "f"(x));
    return __uint_as_float(r);
}
#define CP_ASYNC16(dst, src) \
    asm volatile("cp.async.cg.shared.global [%0], [%1], 16;\n" :: "r"(dst), "l"(src))
#define CP_COMMIT() asm volatile("cp.async.commit_group;" ::: "memory")
#define CP_WAIT(n)  asm volatile("cp.async.wait_group %0;" :: "n"(n) : "memory")

// m16n8k8 tf32 MMA (row.col), fp32 accumulate
__device__ __forceinline__ void mma_tf32(float* c, const uint32_t* a, const uint32_t* b) {
    asm volatile(
        "mma.sync.aligned.m16n8k8.row.col.f32.tf32.tf32.f32 "
        "{%0,%1,%2,%3}, {%4,%5,%6,%7}, {%8,%9}, {%0,%1,%2,%3};"
        : "+f"(c[0]), "+f"(c[1]), "+f"(c[2]), "+f"(c[3])
        : "r"(a[0]), "r"(a[1]), "r"(a[2]), "r"(a[3]), "r"(b[0]), "r"(b[1]));
}

// ---------------------------------------------------------------- prep
__global__ void round_tf32_kernel(const float* __restrict__ in, float* __restrict__ out) {
    size_t i = ((size_t)blockIdx.x * blockDim.x + threadIdx.x) * 4;
    float4 v = *(const float4*)(in + i);
    v.x = rn_tf32(v.x); v.y = rn_tf32(v.y); v.z = rn_tf32(v.z); v.w = rn_tf32(v.w);
    *(float4*)(out + i) = v;
}

// ---------------------------------------------------------------- tf32 GEMM
// C[M,N] = A[M,K] @ B[K,N] + bias[N].  128x128 tile, BK=32, 4-stage cp.async.
#define GBM 128
#define GBN 128
#define GBK 32
#define GSTG 4
#define AS_STRIDE 36            // 36 % 32 == 4 -> A frag reads (4g+t) conflict-free
#define BS_STRIDE 136           // 136 % 32 == 8 -> B frag reads (8t+g) conflict-free
#define AS_TILE (GBM * AS_STRIDE)   // 4608 floats
#define BS_TILE (GBK * BS_STRIDE)   // 4352 floats
#define GEMM_SMEM (GSTG * (AS_TILE + BS_TILE) * 4)   // 143360 B

__device__ __forceinline__ void gemm_load_stage(
    float* As, float* Bs, const float* A, const float* B,
    int m0, int n0, int K, int N, int kb, int tid)
{
    int s = kb & (GSTG - 1);
    uint32_t abase = smem_u32(As + s * AS_TILE);
    uint32_t bbase = smem_u32(Bs + s * BS_TILE);
    const float* ag = A + (size_t)m0 * K + (size_t)kb * GBK;
    const float* bg = B + (size_t)kb * GBK * N + n0;
#pragma unroll
    for (int i = 0; i < 4; i++) {           // A: 128 rows x 32 cols
        int idx = tid + i * 256;
        int row = idx >> 3, c4 = idx & 7;
        CP_ASYNC16(abase + (row * AS_STRIDE + c4 * 4) * 4,
                   ag + (size_t)row * K + c4 * 4);
    }
#pragma unroll
    for (int i = 0; i < 4; i++) {           // B: 32 rows x 128 cols
        int idx = tid + i * 256;
        int row = idx >> 5, c4 = idx & 31;
        CP_ASYNC16(bbase + (row * BS_STRIDE + c4 * 4) * 4,
                   bg + (size_t)row * N + c4 * 4);
    }
}

__global__ __launch_bounds__(256, 1) void gemm_tf32(
    const float* __restrict__ A, const float* __restrict__ B,
    const float* __restrict__ bias, float* __restrict__ C,
    int M, int N, int K, int round_out)
{
    extern __shared__ float smf[];
    float* As = smf;
    float* Bs = smf + GSTG * AS_TILE;

    const int tid = threadIdx.x, wid = tid >> 5, lane = tid & 31;
    const int g = lane >> 2, t = lane & 3;
    const int wm = wid & 3, wn = wid >> 2;            // 4 x 2 warps
    const int m0 = blockIdx.y * GBM, n0 = blockIdx.x * GBN;
    const int NCH = K / GBK;

    float acc[2][8][4];
#pragma unroll
    for (int mt = 0; mt < 2; mt++)
#pragma unroll
        for (int nt = 0; nt < 8; nt++)
#pragma unroll
            for (int k = 0; k < 4; k++) acc[mt][nt][k] = 0.f;

    // prologue: stages 0..GSTG-2
#pragma unroll
    for (int s = 0; s < GSTG - 1; s++) {
        gemm_load_stage(As, Bs, A, B, m0, n0, K, N, s, tid);
        CP_COMMIT();
    }

    for (int kb = 0; kb < NCH; kb++) {
        CP_WAIT(GSTG - 2);          // RACE FIX: retire oldest group -> stage kb resident
        __syncthreads();

        if (kb + GSTG - 1 < NCH)
            gemm_load_stage(As, Bs, A, B, m0, n0, K, N, kb + GSTG - 1, tid);
        CP_COMMIT();

        const float* as = As + (kb & (GSTG - 1)) * AS_TILE;
        const float* bs = Bs + (kb & (GSTG - 1)) * BS_TILE;
#pragma unroll
        for (int ks = 0; ks < 4; ks++) {
            uint32_t af[2][4], bf[8][2];
#pragma unroll
            for (int mt = 0; mt < 2; mt++) {
                int r = wm * 32 + mt * 16 + g;
                int c = ks * 8 + t;
                af[mt][0] = __float_as_uint(as[(size_t)r * AS_STRIDE + c]);
                af[mt][1] = __float_as_uint(as[(size_t)(r + 8) * AS_STRIDE + c]);
                af[mt][2] = __float_as_uint(as[(size_t)r * AS_STRIDE + c + 4]);
                af[mt][3] = __float_as_uint(as[(size_t)(r + 8) * AS_STRIDE + c + 4]);
            }
#pragma unroll
            for (int nt = 0; nt < 8; nt++) {
                int cc = wn * 64 + nt * 8 + g;
                int r = ks * 8 + t;
                bf[nt][0] = __float_as_uint(bs[(size_t)r * BS_STRIDE + cc]);
                bf[nt][1] = __float_as_uint(bs[(size_t)(r + 4) * BS_STRIDE + cc]);
            }
#pragma unroll
            for (int mt = 0; mt < 2; mt++)
#pragma unroll
                for (int nt = 0; nt < 8; nt++)
                    mma_tf32(acc[mt][nt], af[mt], bf[nt]);
        }
    }

    // epilogue: bias + (optional tf32 round) + store
#pragma unroll
    for (int mt = 0; mt < 2; mt++) {
        int r0 = m0 + wm * 32 + mt * 16 + g;
#pragma unroll
        for (int nt = 0; nt < 8; nt++) {
            int c = n0 + wn * 64 + nt * 8 + 2 * t;
            float2 b2 = *(const float2*)(bias + c);
            float2 v0 = make_float2(acc[mt][nt][0] + b2.x, acc[mt][nt][1] + b2.y);
            float2 v1 = make_float2(acc[mt][nt][2] + b2.x, acc[mt][nt][3] + b2.y);
            if (round_out) {
                v0.x = rn_tf32(v0.x); v0.y = rn_tf32(v0.y);
                v1.x = rn_tf32(v1.x); v1.y = rn_tf32(v1.y);
            }
            *(float2*)(C + (size_t)r0 * N + c) = v0;
            *(float2*)(C + (size_t)(r0 + 8) * N + c) = v1;
        }
    }
}

// ---------------------------------------------------------------- attention (tf32 tensor)
// 128 threads / 4 warps per (64-row q-tile, head, batch). Warp w owns Q rows
// [16w,16w+16). S and PV via m16n8k8 tf32. K/V tiles double-buffered cp.async.
// Strides: Qs/Ks/Ps 68 (bank 4g+t conflict-free), Vs 72 (bank 8t+g conflict-free).
#define AQ 64
#define AK 64
#define QS_STR 68
#define KS_STR 68
#define VS_STR 72
#define PS_STR 68
#define SM_QS 0
#define SM_KS (AQ*QS_STR)                    // 4352
#define SM_VS (SM_KS + 2*AK*KS_STR)          // 13056
#define SM_PS (SM_VS + 2*AK*VS_STR)          // 22272
#define ATTN_SMEM ((SM_PS + AQ*PS_STR) * 4)  // 106496 B

__device__ __forceinline__ void attn_load_kv(float* sm, const float* __restrict__ qkv,
                                             int b, int h, int kt, int buf, int tid)
{
    const float* kbase = qkv + ((size_t)(b * TT + kt * AK)) * C3 + CC + h * HD;
    const float* vbase = kbase + CC;
    uint32_t kdst = smem_u32(sm + SM_KS + buf * AK * KS_STR);
    uint32_t vdst = smem_u32(sm + SM_VS + buf * AK * VS_STR);
#pragma unroll
    for (int i = 0; i < 8; i++) {
        int idx = tid + i * 128;
        int row = idx >> 4, c4 = idx & 15;
        CP_ASYNC16(kdst + (row * KS_STR + c4 * 4) * 4, kbase + (size_t)row * C3 + c4 * 4);
        CP_ASYNC16(vdst + (row * VS_STR + c4 * 4) * 4, vbase + (size_t)row * C3 + c4 * 4);
    }
}

__global__ __launch_bounds__(128) void attn_tc(const float* __restrict__ qkv,
                                               float* __restrict__ y)
{
    extern __shared__ float sm[];
    const int tid = threadIdx.x;
    const int wid = tid >> 5, lane = tid & 31;
    const int g = lane >> 2, t = lane & 3;
    const int qt = gridDim.x - 1 - blockIdx.x;   // longest blocks first
    const int h  = blockIdx.y;
    const int b  = blockIdx.z;
    const int q0 = qt * AQ;
    const int r0 = wid * 16 + g;                 // local row of c0/c1

    // stage Q (scaled; qkv is already tf32-clean, scale 0.125 exact)
    {
        const float* qbase = qkv + ((size_t)(b * TT + q0)) * C3 + h * HD;
#pragma unroll
        for (int i = 0; i < 8; i++) {
            int idx = tid + i * 128;
            int row = idx >> 4, c4 = idx & 15;
            float4 v = *(const float4*)(qbase + (size_t)row * C3 + c4 * 4);
            v.x *= SCALE; v.y *= SCALE; v.z *= SCALE; v.w *= SCALE;
            *(float4*)(&sm[SM_QS + row * QS_STR + c4 * 4]) = v;
        }
    }
    // prologue: K/V tile 0
    attn_load_kv(sm, qkv, b, h, 0, 0, tid);
    CP_COMMIT();
    __syncthreads();

    // Q fragments (registers, reused every tile)
    uint32_t qf[8][4];
#pragma unroll
    for (int ds = 0; ds < 8; ds++) {
        qf[ds][0] = __float_as_uint(sm[SM_QS + r0 * QS_STR + ds * 8 + t]);
        qf[ds][1] = __float_as_uint(sm[SM_QS + (r0 + 8) * QS_STR + ds * 8 + t]);
        qf[ds][2] = __float_as_uint(sm[SM_QS + r0 * QS_STR + ds * 8 + t + 4]);
        qf[ds][3] = __float_as_uint(sm[SM_QS + (r0 + 8) * QS_STR + ds * 8 + t + 4]);
    }

    float oacc[8][4];
#pragma unroll
    for (int nt = 0; nt < 8; nt++)
#pragma unroll
        for (int k = 0; k < 4; k++) oacc[nt][k] = 0.f;
    float mrow0 = -INFINITY, mrow1 = -INFINITY, lrow0 = 0.f, lrow1 = 0.f;

    for (int kt = 0; kt <= qt; kt++) {
        const int buf = kt & 1;
        CP_WAIT(0);
        __syncthreads();
        if (kt < qt) { attn_load_kv(sm, qkv, b, h, kt + 1, buf ^ 1, tid); CP_COMMIT(); }

        const float* ks = sm + SM_KS + buf * AK * KS_STR;
        const float* vs = sm + SM_VS + buf * AK * VS_STR;

        // S = Q K^T
        float sacc[8][4];
#pragma unroll
        for (int nt = 0; nt < 8; nt++)
#pragma unroll
            for (int k = 0; k < 4; k++) sacc[nt][k] = 0.f;
#pragma unroll
        for (int ds = 0; ds < 8; ds++) {
            uint32_t bf[8][2];
#pragma unroll
            for (int nt = 0; nt < 8; nt++) {
                bf[nt][0] = __float_as_uint(ks[(nt * 8 + g) * KS_STR + ds * 8 + t]);
                bf[nt][1] = __float_as_uint(ks[(nt * 8 + g) * KS_STR + ds * 8 + t + 4]);
            }
#pragma unroll
            for (int nt = 0; nt < 8; nt++)
                mma_tf32(sacc[nt], qf[ds], bf[nt]);
        }

        // causal mask (diagonal tile; local row vs local col since q0 == kt*64)
        if (kt == qt) {
#pragma unroll
            for (int nt = 0; nt < 8; nt++) {
                int c = nt * 8 + 2 * t;
                if (c     > r0)     sacc[nt][0] = -1e30f;
                if (c + 1 > r0)     sacc[nt][1] = -1e30f;
                if (c     > r0 + 8) sacc[nt][2] = -1e30f;
                if (c + 1 > r0 + 8) sacc[nt][3] = -1e30f;
            }
        }

        // online softmax (rows r0 and r0+8); quad = lanes sharing g
        float tm0 = -INFINITY, tm1 = -INFINITY;
#pragma unroll
        for (int nt = 0; nt < 8; nt++) {
            tm0 = fmaxf(tm0, fmaxf(sacc[nt][0], sacc[nt][1]));
            tm1 = fmaxf(tm1, fmaxf(sacc[nt][2], sacc[nt][3]));
        }
        tm0 = fmaxf(tm0, __shfl_xor_sync(0xffffffffu, tm0, 1));
        tm0 = fmaxf(tm0, __shfl_xor_sync(0xffffffffu, tm0, 2));
        tm1 = fmaxf(tm1, __shfl_xor_sync(0xffffffffu, tm1, 1));
        tm1 = fmaxf(tm1, __shfl_xor_sync(0xffffffffu, tm1, 2));
        float m0 = fmaxf(mrow0, tm0), m1 = fmaxf(mrow1, tm1);
        float a0 = __expf(mrow0 - m0), a1 = __expf(mrow1 - m1);
        mrow0 = m0; mrow1 = m1;
        float rs0 = 0.f, rs1 = 0.f;
#pragma unroll
        for (int nt = 0; nt < 8; nt++) {
            sacc[nt][0] = __expf(sacc[nt][0] - m0); rs0 += sacc[nt][0];
            sacc[nt][1] = __expf(sacc[nt][1] - m0); rs0 += sacc[nt][1];
            sacc[nt][2] = __expf(sacc[nt][2] - m1); rs1 += sacc[nt][2];
            sacc[nt][3] = __expf(sacc[nt][3] - m1); rs1 += sacc[nt][3];
        }
        rs0 += __shfl_xor_sync(0xffffffffu, rs0, 1);
        rs0 += __shfl_xor_sync(0xffffffffu, rs0, 2);
        rs1 += __shfl_xor_sync(0xffffffffu, rs1, 1);
        rs1 += __shfl_xor_sync(0xffffffffu, rs1, 2);
        lrow0 = lrow0 * a0 + rs0;
        lrow1 = lrow1 * a1 + rs1;
#pragma unroll
        for (int nt = 0; nt < 8; nt++) {
            oacc[nt][0] *= a0; oacc[nt][1] *= a0;
            oacc[nt][2] *= a1; oacc[nt][3] *= a1;
        }

        // stage P (tf32-rounded) into per-warp Ps rows
#pragma unroll
        for (int nt = 0; nt < 8; nt++) {
            float2 p0 = make_float2(rn_tf32(sacc[nt][0]), rn_tf32(sacc[nt][1]));
            float2 p1 = make_float2(rn_tf32(sacc[nt][2]), rn_tf32(sacc[nt][3]));
            *(float2*)(&sm[SM_PS + r0 * PS_STR + nt * 8 + 2 * t]) = p0;
            *(float2*)(&sm[SM_PS + (r0 + 8) * PS_STR + nt * 8 + 2 * t]) = p1;
        }
        __syncwarp();

        // O += P @ V
#pragma unroll
        for (int kk = 0; kk < 8; kk++) {
            uint32_t af[4];
            af[0] = __float_as_uint(sm[SM_PS + r0 * PS_STR + kk * 8 + t]);
            af[1] = __float_as_uint(sm[SM_PS + (r0 + 8) * PS_STR + kk * 8 + t]);
            af[2] = __float_as_uint(sm[SM_PS + r0 * PS_STR + kk * 8 + t + 4]);
            af[3] = __float_as_uint(sm[SM_PS + (r0 + 8) * PS_STR + kk * 8 + t + 4]);
            uint32_t bf[8][2];
#pragma unroll
            for (int nt = 0; nt < 8; nt++) {
                bf[nt][0] = __float_as_uint(vs[(kk * 8 + t) * VS_STR + nt * 8 + g]);
                bf[nt][1] = __float_as_uint(vs[(kk * 8 + t + 4) * VS_STR + nt * 8 + g]);
            }
#pragma unroll
            for (int nt = 0; nt < 8; nt++)
                mma_tf32(oacc[nt], af, bf[nt]);
        }
    }

    // normalize + store (tf32-rounded: feeds tf32 proj GEMM)
    float inv0 = 1.0f / lrow0, inv1 = 1.0f / lrow1;
    float* ybase = y + ((size_t)(b * TT + q0)) * CC + h * HD;
#pragma unroll
    for (int nt = 0; nt < 8; nt++) {
        float2 v0 = make_float2(rn_tf32(oacc[nt][0] * inv0), rn_tf32(oacc[nt][1] * inv0));
        float2 v1 = make_float2(rn_tf32(oacc[nt][2] * inv1), rn_tf32(oacc[nt][3] * inv1));
        *(float2*)(ybase + (size_t)r0 * CC + nt * 8 + 2 * t) = v0;
        *(float2*)(ybase + (size_t)(r0 + 8) * CC + nt * 8 + 2 * t) = v1;
    }
}

// ---------------------------------------------------------------- launch
extern "C" void kernel_launch(void* const* d_in, const int* in_sizes, int n_in,
                              void* d_out, int out_size)
{
    const float* x      = (const float*)d_in[0];
    const float* w_attn = (const float*)d_in[1];
    const float* b_attn = (const float*)d_in[2];
    const float* w_proj = (const float*)d_in[3];
    const float* b_proj = (const float*)d_in[4];
    float* out = (float*)d_out;

    float *qkv, *yb, *xr, *wa, *wp;
    cudaGetSymbolAddress((void**)&qkv, g_qkv);
    cudaGetSymbolAddress((void**)&yb,  g_y);
    cudaGetSymbolAddress((void**)&xr,  g_xr);
    cudaGetSymbolAddress((void**)&wa,  g_wa);
    cudaGetSymbolAddress((void**)&wp,  g_wp);

    cudaFuncSetAttribute(gemm_tf32, cudaFuncAttributeMaxDynamicSharedMemorySize, GEMM_SMEM);
    cudaFuncSetAttribute(attn_tc,   cudaFuncAttributeMaxDynamicSharedMemorySize, ATTN_SMEM);

    // 0) round operands to tf32
    round_tf32_kernel<<<(BT * CC) / 1024, 256>>>(x, xr);
    round_tf32_kernel<<<(CC * C3) / 1024, 256>>>(w_attn, wa);
    round_tf32_kernel<<<(CC * CC) / 1024, 256>>>(w_proj, wp);

    // 1) QKV = x @ w_attn + b_attn   (tf32 mma.sync; output rounded to tf32)
    gemm_tf32<<<dim3(C3 / GBN, BT / GBM), 256, GEMM_SMEM>>>(xr, wa, b_attn, qkv,
                                                            BT, C3, CC, 1);

    // 2) causal attention (tf32 tensor cores)
    attn_tc<<<dim3(TT / AQ, NH, BB), 128, ATTN_SMEM>>>(qkv, yb);

    // 3) out = y @ w_proj + b_proj   (tf32 mma.sync; fp32 output)
    gemm_tf32<<<dim3(CC / GBN, BT / GBM), 256, GEMM_SMEM>>>(yb, wp, b_proj, out,
                                                            BT, CC, CC, 0);
}

// round 5
// speedup vs baseline: 3.3342x; 1.1531x over previous
#include <cuda_runtime.h>
#include <cstdint>
#include <cmath>

// ---------------------------------------------------------------- constants
#define BB   2
#define TT   2048
#define CC   1024
#define NH   16
#define HD   64
#define BT   (BB*TT)          // 4096
#define C3   (3*CC)           // 3072
#define SCALE 0.125f

// ---------------------------------------------------------------- scratch
__device__ float g_qkv[(size_t)BT * C3];   // [4096,3072] (tf32-clean)
__device__ float g_y  [(size_t)BT * CC];   // attention out (tf32-clean)
__device__ float g_xr [(size_t)BT * CC];   // x rounded to tf32
__device__ float g_wa [(size_t)CC * C3];   // w_attn rounded to tf32
__device__ float g_wp [(size_t)CC * CC];   // w_proj rounded to tf32

// ---------------------------------------------------------------- utils
__device__ __forceinline__ uint32_t smem_u32(const void* p) {
    uint32_t a;
    asm("{ .reg .u64 t; cvta.to.shared.u64 t, %1; cvt.u32.u64 %0, t; }" : "=r"(a) : "l"(p));
    return a;
}
__device__ __forceinline__ float rn_tf32(float x) {
    uint32_t r;
    asm("cvt.rna.tf32.f32 %0, %1;" : "=r"(r) : "f"(x));
    return __uint_as_float(r);
}
#define CP_ASYNC16(dst, src) \
    asm volatile("cp.async.cg.shared.global [%0], [%1], 16;\n" :: "r"(dst), "l"(src))
#define CP_COMMIT() asm volatile("cp.async.commit_group;" ::: "memory")
#define CP_WAIT(n)  asm volatile("cp.async.wait_group %0;" :: "n"(n) : "memory")

// m16n8k8 tf32 MMA (row.col), fp32 accumulate
__device__ __forceinline__ void mma_tf32(float* c, const uint32_t* a, const uint32_t* b) {
    asm volatile(
        "mma.sync.aligned.m16n8k8.row.col.f32.tf32.tf32.f32 "
        "{%0,%1,%2,%3}, {%4,%5,%6,%7}, {%8,%9}, {%0,%1,%2,%3};"
        : "+f"(c[0]), "+f"(c[1]), "+f"(c[2]), "+f"(c[3])
        : "r"(a[0]), "r"(a[1]), "r"(a[2]), "r"(a[3]), "r"(b[0]), "r"(b[1]));
}

// ---------------------------------------------------------------- prep
__global__ void round_tf32_kernel(const float* __restrict__ in, float* __restrict__ out) {
    size_t i = ((size_t)blockIdx.x * blockDim.x + threadIdx.x) * 4;
    float4 v = *(const float4*)(in + i);
    v.x = rn_tf32(v.x); v.y = rn_tf32(v.y); v.z = rn_tf32(v.z); v.w = rn_tf32(v.w);
    *(float4*)(out + i) = v;
}

// ---------------------------------------------------------------- tf32 GEMM
// C[M,N] = A[M,K] @ B[K,N] + bias[N].  128x128 tile, BK=32, 3-stage cp.async,
// 2 CTAs/SM (smem 105KB, regs capped at 128).
#define GBM 128
#define GBN 128
#define GBK 32
#define GSTG 3
#define AS_STRIDE 36            // 36 % 32 == 4 -> A frag reads (4g+t) conflict-free
#define BS_STRIDE 136           // 136 % 32 == 8 -> B frag reads (8t+g) conflict-free
#define AS_TILE (GBM * AS_STRIDE)   // 4608 floats
#define BS_TILE (GBK * BS_STRIDE)   // 4352 floats
#define GEMM_SMEM (GSTG * (AS_TILE + BS_TILE) * 4)   // 107520 B

__device__ __forceinline__ void gemm_load_stage(
    float* As, float* Bs, const float* A, const float* B,
    int m0, int n0, int K, int N, int kb, int tid)
{
    int s = kb % GSTG;
    uint32_t abase = smem_u32(As + s * AS_TILE);
    uint32_t bbase = smem_u32(Bs + s * BS_TILE);
    const float* ag = A + (size_t)m0 * K + (size_t)kb * GBK;
    const float* bg = B + (size_t)kb * GBK * N + n0;
#pragma unroll
    for (int i = 0; i < 4; i++) {           // A: 128 rows x 32 cols
        int idx = tid + i * 256;
        int row = idx >> 3, c4 = idx & 7;
        CP_ASYNC16(abase + (row * AS_STRIDE + c4 * 4) * 4,
                   ag + (size_t)row * K + c4 * 4);
    }
#pragma unroll
    for (int i = 0; i < 4; i++) {           // B: 32 rows x 128 cols
        int idx = tid + i * 256;
        int row = idx >> 5, c4 = idx & 31;
        CP_ASYNC16(bbase + (row * BS_STRIDE + c4 * 4) * 4,
                   bg + (size_t)row * N + c4 * 4);
    }
}

__global__ __launch_bounds__(256, 2) void gemm_tf32(
    const float* __restrict__ A, const float* __restrict__ B,
    const float* __restrict__ bias, float* __restrict__ C,
    int M, int N, int K, int round_out)
{
    extern __shared__ float smf[];
    float* As = smf;
    float* Bs = smf + GSTG * AS_TILE;

    const int tid = threadIdx.x, wid = tid >> 5, lane = tid & 31;
    const int g = lane >> 2, t = lane & 3;
    const int wm = wid & 3, wn = wid >> 2;            // 4 x 2 warps
    const int m0 = blockIdx.y * GBM, n0 = blockIdx.x * GBN;
    const int NCH = K / GBK;

    float acc[2][8][4];
#pragma unroll
    for (int mt = 0; mt < 2; mt++)
#pragma unroll
        for (int nt = 0; nt < 8; nt++)
#pragma unroll
            for (int k = 0; k < 4; k++) acc[mt][nt][k] = 0.f;

    // prologue: stages 0..GSTG-2
#pragma unroll
    for (int s = 0; s < GSTG - 1; s++) {
        gemm_load_stage(As, Bs, A, B, m0, n0, K, N, s, tid);
        CP_COMMIT();
    }

    for (int kb = 0; kb < NCH; kb++) {
        CP_WAIT(GSTG - 2);          // retire oldest group -> stage kb resident
        __syncthreads();

        if (kb + GSTG - 1 < NCH)
            gemm_load_stage(As, Bs, A, B, m0, n0, K, N, kb + GSTG - 1, tid);
        CP_COMMIT();

        const float* as = As + (kb % GSTG) * AS_TILE;
        const float* bs = Bs + (kb % GSTG) * BS_TILE;
#pragma unroll
        for (int ks = 0; ks < 4; ks++) {
            uint32_t af[2][4], bf[8][2];
#pragma unroll
            for (int mt = 0; mt < 2; mt++) {
                int r = wm * 32 + mt * 16 + g;
                int c = ks * 8 + t;
                af[mt][0] = __float_as_uint(as[(size_t)r * AS_STRIDE + c]);
                af[mt][1] = __float_as_uint(as[(size_t)(r + 8) * AS_STRIDE + c]);
                af[mt][2] = __float_as_uint(as[(size_t)r * AS_STRIDE + c + 4]);
                af[mt][3] = __float_as_uint(as[(size_t)(r + 8) * AS_STRIDE + c + 4]);
            }
#pragma unroll
            for (int nt = 0; nt < 8; nt++) {
                int cc = wn * 64 + nt * 8 + g;
                int r = ks * 8 + t;
                bf[nt][0] = __float_as_uint(bs[(size_t)r * BS_STRIDE + cc]);
                bf[nt][1] = __float_as_uint(bs[(size_t)(r + 4) * BS_STRIDE + cc]);
            }
#pragma unroll
            for (int mt = 0; mt < 2; mt++)
#pragma unroll
                for (int nt = 0; nt < 8; nt++)
                    mma_tf32(acc[mt][nt], af[mt], bf[nt]);
        }
    }

    // epilogue: bias + (optional tf32 round) + store
#pragma unroll
    for (int mt = 0; mt < 2; mt++) {
        int r0 = m0 + wm * 32 + mt * 16 + g;
#pragma unroll
        for (int nt = 0; nt < 8; nt++) {
            int c = n0 + wn * 64 + nt * 8 + 2 * t;
            float2 b2 = *(const float2*)(bias + c);
            float2 v0 = make_float2(acc[mt][nt][0] + b2.x, acc[mt][nt][1] + b2.y);
            float2 v1 = make_float2(acc[mt][nt][2] + b2.x, acc[mt][nt][3] + b2.y);
            if (round_out) {
                v0.x = rn_tf32(v0.x); v0.y = rn_tf32(v0.y);
                v1.x = rn_tf32(v1.x); v1.y = rn_tf32(v1.y);
            }
            *(float2*)(C + (size_t)r0 * N + c) = v0;
            *(float2*)(C + (size_t)(r0 + 8) * N + c) = v1;
        }
    }
}

// ---------------------------------------------------------------- attention (tf32 tensor)
// 128 threads / 4 warps per (64-row q-tile, head, batch). Warp w owns Q rows
// [16w,16w+16). S and PV via m16n8k8 tf32. K/V tiles double-buffered cp.async.
// 2 CTAs/SM (smem 106.5KB x2 fits 228KB; regs capped at 256).
#define AQ 64
#define AK 64
#define QS_STR 68
#define KS_STR 68
#define VS_STR 72
#define PS_STR 68
#define SM_QS 0
#define SM_KS (AQ*QS_STR)                    // 4352
#define SM_VS (SM_KS + 2*AK*KS_STR)          // 13056
#define SM_PS (SM_VS + 2*AK*VS_STR)          // 22272
#define ATTN_SMEM ((SM_PS + AQ*PS_STR) * 4)  // 106496 B

__device__ __forceinline__ void attn_load_kv(float* sm, const float* __restrict__ qkv,
                                             int b, int h, int kt, int buf, int tid)
{
    const float* kbase = qkv + ((size_t)(b * TT + kt * AK)) * C3 + CC + h * HD;
    const float* vbase = kbase + CC;
    uint32_t kdst = smem_u32(sm + SM_KS + buf * AK * KS_STR);
    uint32_t vdst = smem_u32(sm + SM_VS + buf * AK * VS_STR);
#pragma unroll
    for (int i = 0; i < 8; i++) {
        int idx = tid + i * 128;
        int row = idx >> 4, c4 = idx & 15;
        CP_ASYNC16(kdst + (row * KS_STR + c4 * 4) * 4, kbase + (size_t)row * C3 + c4 * 4);
        CP_ASYNC16(vdst + (row * VS_STR + c4 * 4) * 4, vbase + (size_t)row * C3 + c4 * 4);
    }
}

__global__ __launch_bounds__(128, 2) void attn_tc(const float* __restrict__ qkv,
                                                  float* __restrict__ y)
{
    extern __shared__ float sm[];
    const int tid = threadIdx.x;
    const int wid = tid >> 5, lane = tid & 31;
    const int g = lane >> 2, t = lane & 3;
    const int qt = gridDim.x - 1 - blockIdx.x;   // longest blocks first
    const int h  = blockIdx.y;
    const int b  = blockIdx.z;
    const int q0 = qt * AQ;
    const int r0 = wid * 16 + g;                 // local row of c0/c1

    // stage Q (scaled; qkv is already tf32-clean, scale 0.125 exact)
    {
        const float* qbase = qkv + ((size_t)(b * TT + q0)) * C3 + h * HD;
#pragma unroll
        for (int i = 0; i < 8; i++) {
            int idx = tid + i * 128;
            int row = idx >> 4, c4 = idx & 15;
            float4 v = *(const float4*)(qbase + (size_t)row * C3 + c4 * 4);
            v.x *= SCALE; v.y *= SCALE; v.z *= SCALE; v.w *= SCALE;
            *(float4*)(&sm[SM_QS + row * QS_STR + c4 * 4]) = v;
        }
    }
    // prologue: K/V tile 0
    attn_load_kv(sm, qkv, b, h, 0, 0, tid);
    CP_COMMIT();
    __syncthreads();

    // Q fragments (registers, reused every tile)
    uint32_t qf[8][4];
#pragma unroll
    for (int ds = 0; ds < 8; ds++) {
        qf[ds][0] = __float_as_uint(sm[SM_QS + r0 * QS_STR + ds * 8 + t]);
        qf[ds][1] = __float_as_uint(sm[SM_QS + (r0 + 8) * QS_STR + ds * 8 + t]);
        qf[ds][2] = __float_as_uint(sm[SM_QS + r0 * QS_STR + ds * 8 + t + 4]);
        qf[ds][3] = __float_as_uint(sm[SM_QS + (r0 + 8) * QS_STR + ds * 8 + t + 4]);
    }

    float oacc[8][4];
#pragma unroll
    for (int nt = 0; nt < 8; nt++)
#pragma unroll
        for (int k = 0; k < 4; k++) oacc[nt][k] = 0.f;
    float mrow0 = -INFINITY, mrow1 = -INFINITY, lrow0 = 0.f, lrow1 = 0.f;

    for (int kt = 0; kt <= qt; kt++) {
        const int buf = kt & 1;
        CP_WAIT(0);
        __syncthreads();
        if (kt < qt) { attn_load_kv(sm, qkv, b, h, kt + 1, buf ^ 1, tid); CP_COMMIT(); }

        const float* ks = sm + SM_KS + buf * AK * KS_STR;
        const float* vs = sm + SM_VS + buf * AK * VS_STR;

        // S = Q K^T
        float sacc[8][4];
#pragma unroll
        for (int nt = 0; nt < 8; nt++)
#pragma unroll
            for (int k = 0; k < 4; k++) sacc[nt][k] = 0.f;
#pragma unroll
        for (int ds = 0; ds < 8; ds++) {
            uint32_t bf[8][2];
#pragma unroll
            for (int nt = 0; nt < 8; nt++) {
                bf[nt][0] = __float_as_uint(ks[(nt * 8 + g) * KS_STR + ds * 8 + t]);
                bf[nt][1] = __float_as_uint(ks[(nt * 8 + g) * KS_STR + ds * 8 + t + 4]);
            }
#pragma unroll
            for (int nt = 0; nt < 8; nt++)
                mma_tf32(sacc[nt], qf[ds], bf[nt]);
        }

        // causal mask (diagonal tile; local row vs local col since q0 == kt*64)
        if (kt == qt) {
#pragma unroll
            for (int nt = 0; nt < 8; nt++) {
                int c = nt * 8 + 2 * t;
                if (c     > r0)     sacc[nt][0] = -1e30f;
                if (c + 1 > r0)     sacc[nt][1] = -1e30f;
                if (c     > r0 + 8) sacc[nt][2] = -1e30f;
                if (c + 1 > r0 + 8) sacc[nt][3] = -1e30f;
            }
        }

        // online softmax (rows r0 and r0+8); quad = lanes sharing g
        float tm0 = -INFINITY, tm1 = -INFINITY;
#pragma unroll
        for (int nt = 0; nt < 8; nt++) {
            tm0 = fmaxf(tm0, fmaxf(sacc[nt][0], sacc[nt][1]));
            tm1 = fmaxf(tm1, fmaxf(sacc[nt][2], sacc[nt][3]));
        }
        tm0 = fmaxf(tm0, __shfl_xor_sync(0xffffffffu, tm0, 1));
        tm0 = fmaxf(tm0, __shfl_xor_sync(0xffffffffu, tm0, 2));
        tm1 = fmaxf(tm1, __shfl_xor_sync(0xffffffffu, tm1, 1));
        tm1 = fmaxf(tm1, __shfl_xor_sync(0xffffffffu, tm1, 2));
        float m0 = fmaxf(mrow0, tm0), m1 = fmaxf(mrow1, tm1);
        float a0 = __expf(mrow0 - m0), a1 = __expf(mrow1 - m1);
        mrow0 = m0; mrow1 = m1;
        float rs0 = 0.f, rs1 = 0.f;
#pragma unroll
        for (int nt = 0; nt < 8; nt++) {
            sacc[nt][0] = __expf(sacc[nt][0] - m0); rs0 += sacc[nt][0];
            sacc[nt][1] = __expf(sacc[nt][1] - m0); rs0 += sacc[nt][1];
            sacc[nt][2] = __expf(sacc[nt][2] - m1); rs1 += sacc[nt][2];
            sacc[nt][3] = __expf(sacc[nt][3] - m1); rs1 += sacc[nt][3];
        }
        rs0 += __shfl_xor_sync(0xffffffffu, rs0, 1);
        rs0 += __shfl_xor_sync(0xffffffffu, rs0, 2);
        rs1 += __shfl_xor_sync(0xffffffffu, rs1, 1);
        rs1 += __shfl_xor_sync(0xffffffffu, rs1, 2);
        lrow0 = lrow0 * a0 + rs0;
        lrow1 = lrow1 * a1 + rs1;
#pragma unroll
        for (int nt = 0; nt < 8; nt++) {
            oacc[nt][0] *= a0; oacc[nt][1] *= a0;
            oacc[nt][2] *= a1; oacc[nt][3] *= a1;
        }

        // stage P (tf32-rounded) into per-warp Ps rows
#pragma unroll
        for (int nt = 0; nt < 8; nt++) {
            float2 p0 = make_float2(rn_tf32(sacc[nt][0]), rn_tf32(sacc[nt][1]));
            float2 p1 = make_float2(rn_tf32(sacc[nt][2]), rn_tf32(sacc[nt][3]));
            *(float2*)(&sm[SM_PS + r0 * PS_STR + nt * 8 + 2 * t]) = p0;
            *(float2*)(&sm[SM_PS + (r0 + 8) * PS_STR + nt * 8 + 2 * t]) = p1;
        }
        __syncwarp();

        // O += P @ V
#pragma unroll
        for (int kk = 0; kk < 8; kk++) {
            uint32_t af[4];
            af[0] = __float_as_uint(sm[SM_PS + r0 * PS_STR + kk * 8 + t]);
            af[1] = __float_as_uint(sm[SM_PS + (r0 + 8) * PS_STR + kk * 8 + t]);
            af[2] = __float_as_uint(sm[SM_PS + r0 * PS_STR + kk * 8 + t + 4]);
            af[3] = __float_as_uint(sm[SM_PS + (r0 + 8) * PS_STR + kk * 8 + t + 4]);
            uint32_t bf[8][2];
#pragma unroll
            for (int nt = 0; nt < 8; nt++) {
                bf[nt][0] = __float_as_uint(vs[(kk * 8 + t) * VS_STR + nt * 8 + g]);
                bf[nt][1] = __float_as_uint(vs[(kk * 8 + t + 4) * VS_STR + nt * 8 + g]);
            }
#pragma unroll
            for (int nt = 0; nt < 8; nt++)
                mma_tf32(oacc[nt], af, bf[nt]);
        }
    }

    // normalize + store (tf32-rounded: feeds tf32 proj GEMM)
    float inv0 = 1.0f / lrow0, inv1 = 1.0f / lrow1;
    float* ybase = y + ((size_t)(b * TT + q0)) * CC + h * HD;
#pragma unroll
    for (int nt = 0; nt < 8; nt++) {
        float2 v0 = make_float2(rn_tf32(oacc[nt][0] * inv0), rn_tf32(oacc[nt][1] * inv0));
        float2 v1 = make_float2(rn_tf32(oacc[nt][2] * inv1), rn_tf32(oacc[nt][3] * inv1));
        *(float2*)(ybase + (size_t)r0 * CC + nt * 8 + 2 * t) = v0;
        *(float2*)(ybase + (size_t)(r0 + 8) * CC + nt * 8 + 2 * t) = v1;
    }
}

// ---------------------------------------------------------------- launch
extern "C" void kernel_launch(void* const* d_in, const int* in_sizes, int n_in,
                              void* d_out, int out_size)
{
    const float* x      = (const float*)d_in[0];
    const float* w_attn = (const float*)d_in[1];
    const float* b_attn = (const float*)d_in[2];
    const float* w_proj = (const float*)d_in[3];
    const float* b_proj = (const float*)d_in[4];
    float* out = (float*)d_out;

    float *qkv, *yb, *xr, *wa, *wp;
    cudaGetSymbolAddress((void**)&qkv, g_qkv);
    cudaGetSymbolAddress((void**)&yb,  g_y);
    cudaGetSymbolAddress((void**)&xr,  g_xr);
    cudaGetSymbolAddress((void**)&wa,  g_wa);
    cudaGetSymbolAddress((void**)&wp,  g_wp);

    cudaFuncSetAttribute(gemm_tf32, cudaFuncAttributeMaxDynamicSharedMemorySize, GEMM_SMEM);
    cudaFuncSetAttribute(attn_tc,   cudaFuncAttributeMaxDynamicSharedMemorySize, ATTN_SMEM);

    // 0) round operands to tf32
    round_tf32_kernel<<<(BT * CC) / 1024, 256>>>(x, xr);
    round_tf32_kernel<<<(CC * C3) / 1024, 256>>>(w_attn, wa);
    round_tf32_kernel<<<(CC * CC) / 1024, 256>>>(w_proj, wp);

    // 1) QKV = x @ w_attn + b_attn   (tf32 mma.sync; output rounded to tf32)
    gemm_tf32<<<dim3(C3 / GBN, BT / GBM), 256, GEMM_SMEM>>>(xr, wa, b_attn, qkv,
                                                            BT, C3, CC, 1);

    // 2) causal attention (tf32 tensor cores)
    attn_tc<<<dim3(TT / AQ, NH, BB), 128, ATTN_SMEM>>>(qkv, yb);

    // 3) out = y @ w_proj + b_proj   (tf32 mma.sync; fp32 output)
    gemm_tf32<<<dim3(CC / GBN, BT / GBM), 256, GEMM_SMEM>>>(yb, wp, b_proj, out,
                                                            BT, CC, CC, 0);
}

// round 6
// speedup vs baseline: 3.3818x; 1.0143x over previous
#include <cuda_runtime.h>
#include <cstdint>
#include <cmath>

// ---------------------------------------------------------------- constants
#define BB   2
#define TT   2048
#define CC   1024
#define NH   16
#define HD   64
#define BT   (BB*TT)          // 4096
#define C3   (3*CC)           // 3072
#define SCALE 0.125f

// ---------------------------------------------------------------- scratch
__device__ float g_qkv[(size_t)BT * C3];   // [4096,3072]; Q,K col-permuted in 8-groups
__device__ float g_y  [(size_t)BT * CC];   // attention out (tf32-clean)
__device__ float g_xr [(size_t)BT * CC];   // x rounded to tf32
__device__ float g_wa [(size_t)CC * C3];   // w_attn rounded to tf32
__device__ float g_wp [(size_t)CC * CC];   // w_proj rounded to tf32

// ---------------------------------------------------------------- utils
__device__ __forceinline__ uint32_t smem_u32(const void* p) {
    uint32_t a;
    asm("{ .reg .u64 t; cvta.to.shared.u64 t, %1; cvt.u32.u64 %0, t; }" : "=r"(a) : "l"(p));
    return a;
}
__device__ __forceinline__ float rn_tf32(float x) {
    uint32_t r;
    asm("cvt.rna.tf32.f32 %0, %1;" : "=r"(r) : "f"(x));
    return __uint_as_float(r);
}
#define CP_ASYNC16(dst, src) \
    asm volatile("cp.async.cg.shared.global [%0], [%1], 16;\n" :: "r"(dst), "l"(src))
#define CP_COMMIT() asm volatile("cp.async.commit_group;" ::: "memory")
#define CP_WAIT(n)  asm volatile("cp.async.wait_group %0;" :: "n"(n) : "memory")

// m16n8k8 tf32 MMA (row.col), fp32 accumulate
__device__ __forceinline__ void mma_tf32(float* c, const uint32_t* a, const uint32_t* b) {
    asm volatile(
        "mma.sync.aligned.m16n8k8.row.col.f32.tf32.tf32.f32 "
        "{%0,%1,%2,%3}, {%4,%5,%6,%7}, {%8,%9}, {%0,%1,%2,%3};"
        : "+f"(c[0]), "+f"(c[1]), "+f"(c[2]), "+f"(c[3])
        : "r"(a[0]), "r"(a[1]), "r"(a[2]), "r"(a[3]), "r"(b[0]), "r"(b[1]));
}

// col permutation within 8-group: [0,4,1,5,2,6,3,7] -> pos(u) = u<4 ? 2u : 2u-7
__device__ __forceinline__ int perm8(int u) { return u < 4 ? 2 * u : 2 * u - 7; }

// ---------------------------------------------------------------- prep
__global__ void round_tf32_kernel(const float* __restrict__ in, float* __restrict__ out) {
    size_t i = ((size_t)blockIdx.x * blockDim.x + threadIdx.x) * 4;
    float4 v = *(const float4*)(in + i);
    v.x = rn_tf32(v.x); v.y = rn_tf32(v.y); v.z = rn_tf32(v.z); v.w = rn_tf32(v.w);
    *(float4*)(out + i) = v;
}

// ---------------------------------------------------------------- tf32 GEMM
// C[M,N] = A[M,K] @ B[K,N] + bias[N].  128x128 tile, BK=32, 3-stage cp.async,
// ks-level register double-buffering, 2 CTAs/SM.
#define GBM 128
#define GBN 128
#define GBK 32
#define GSTG 3
#define AS_STRIDE 36
#define BS_STRIDE 136
#define AS_TILE (GBM * AS_STRIDE)
#define BS_TILE (GBK * BS_STRIDE)
#define GEMM_SMEM (GSTG * (AS_TILE + BS_TILE) * 4)   // 107520 B

__device__ __forceinline__ void gemm_load_stage(
    float* As, float* Bs, const float* A, const float* B,
    int m0, int n0, int K, int N, int kb, int tid)
{
    int s = kb % GSTG;
    uint32_t abase = smem_u32(As + s * AS_TILE);
    uint32_t bbase = smem_u32(Bs + s * BS_TILE);
    const float* ag = A + (size_t)m0 * K + (size_t)kb * GBK;
    const float* bg = B + (size_t)kb * GBK * N + n0;
#pragma unroll
    for (int i = 0; i < 4; i++) {
        int idx = tid + i * 256;
        int row = idx >> 3, c4 = idx & 7;
        CP_ASYNC16(abase + (row * AS_STRIDE + c4 * 4) * 4,
                   ag + (size_t)row * K + c4 * 4);
    }
#pragma unroll
    for (int i = 0; i < 4; i++) {
        int idx = tid + i * 256;
        int row = idx >> 5, c4 = idx & 31;
        CP_ASYNC16(bbase + (row * BS_STRIDE + c4 * 4) * 4,
                   bg + (size_t)row * N + c4 * 4);
    }
}

__device__ __forceinline__ void gemm_load_frags(
    const float* as, const float* bs, int ks, int wm, int wn, int g, int t,
    uint32_t af[2][4], uint32_t bf[8][2])
{
    int c = ks * 8 + t;
#pragma unroll
    for (int mt = 0; mt < 2; mt++) {
        int r = wm * 32 + mt * 16 + g;
        af[mt][0] = __float_as_uint(as[r * AS_STRIDE + c]);
        af[mt][1] = __float_as_uint(as[(r + 8) * AS_STRIDE + c]);
        af[mt][2] = __float_as_uint(as[r * AS_STRIDE + c + 4]);
        af[mt][3] = __float_as_uint(as[(r + 8) * AS_STRIDE + c + 4]);
    }
    int rr = ks * 8 + t;
#pragma unroll
    for (int nt = 0; nt < 8; nt++) {
        int cc = wn * 64 + nt * 8 + g;
        bf[nt][0] = __float_as_uint(bs[rr * BS_STRIDE + cc]);
        bf[nt][1] = __float_as_uint(bs[(rr + 4) * BS_STRIDE + cc]);
    }
}

// perm_qk: permute output cols < 2048 within 8-groups (Q,K regions of qkv)
__global__ __launch_bounds__(256, 2) void gemm_tf32(
    const float* __restrict__ A, const float* __restrict__ B,
    const float* __restrict__ bias, float* __restrict__ C,
    int M, int N, int K, int round_out, int perm_qk)
{
    extern __shared__ float smf[];
    float* As = smf;
    float* Bs = smf + GSTG * AS_TILE;

    const int tid = threadIdx.x, wid = tid >> 5, lane = tid & 31;
    const int g = lane >> 2, t = lane & 3;
    const int wm = wid & 3, wn = wid >> 2;
    const int m0 = blockIdx.y * GBM, n0 = blockIdx.x * GBN;
    const int NCH = K / GBK;

    float acc[2][8][4];
#pragma unroll
    for (int mt = 0; mt < 2; mt++)
#pragma unroll
        for (int nt = 0; nt < 8; nt++)
#pragma unroll
            for (int k = 0; k < 4; k++) acc[mt][nt][k] = 0.f;

#pragma unroll
    for (int s = 0; s < GSTG - 1; s++) {
        gemm_load_stage(As, Bs, A, B, m0, n0, K, N, s, tid);
        CP_COMMIT();
    }

    uint32_t afb[2][2][4], bfb[2][8][2];

    for (int kb = 0; kb < NCH; kb++) {
        CP_WAIT(GSTG - 2);
        __syncthreads();

        const float* as = As + (kb % GSTG) * AS_TILE;
        const float* bs = Bs + (kb % GSTG) * BS_TILE;

        // ks=0 frags first, then overlap LDGSTS issue with their latency
        gemm_load_frags(as, bs, 0, wm, wn, g, t, afb[0], bfb[0]);

        if (kb + GSTG - 1 < NCH)
            gemm_load_stage(As, Bs, A, B, m0, n0, K, N, kb + GSTG - 1, tid);
        CP_COMMIT();

#pragma unroll
        for (int ks = 0; ks < 4; ks++) {
            int cur = ks & 1;
            if (ks < 3)
                gemm_load_frags(as, bs, ks + 1, wm, wn, g, t, afb[cur ^ 1], bfb[cur ^ 1]);
#pragma unroll
            for (int mt = 0; mt < 2; mt++)
#pragma unroll
                for (int nt = 0; nt < 8; nt++)
                    mma_tf32(acc[mt][nt], afb[cur][mt], bfb[cur][nt]);
        }
    }

    // epilogue
#pragma unroll
    for (int mt = 0; mt < 2; mt++) {
        int r0 = m0 + wm * 32 + mt * 16 + g;
#pragma unroll
        for (int nt = 0; nt < 8; nt++) {
            int c = n0 + wn * 64 + nt * 8 + 2 * t;     // even
            float2 b2 = *(const float2*)(bias + c);
            float2 v0 = make_float2(acc[mt][nt][0] + b2.x, acc[mt][nt][1] + b2.y);
            float2 v1 = make_float2(acc[mt][nt][2] + b2.x, acc[mt][nt][3] + b2.y);
            if (round_out) {
                v0.x = rn_tf32(v0.x); v0.y = rn_tf32(v0.y);
                v1.x = rn_tf32(v1.x); v1.y = rn_tf32(v1.y);
            }
            if (perm_qk && c < 2048) {
                int c0p = (c & ~7) | perm8(c & 7);
                int c1p = (c & ~7) | perm8((c & 7) + 1);
                C[(size_t)r0 * N + c0p] = v0.x;
                C[(size_t)r0 * N + c1p] = v0.y;
                C[(size_t)(r0 + 8) * N + c0p] = v1.x;
                C[(size_t)(r0 + 8) * N + c1p] = v1.y;
            } else {
                *(float2*)(C + (size_t)r0 * N + c) = v0;
                *(float2*)(C + (size_t)(r0 + 8) * N + c) = v1;
            }
        }
    }
}

// ---------------------------------------------------------------- attention (tf32 tensor)
// Q,K arrive col-permuted in 8-groups -> S-stage fragment pairs (t,t+4) are
// adjacent -> LDS.64. Strides 72 (8g+2t bijective per phase) conflict-free.
#define AQ 64
#define AK 64
#define QS_STR 72
#define KS_STR 72
#define VS_STR 72
#define PS_STR 68
#define SM_QS 0
#define SM_KS (AQ*QS_STR)                    // 4608
#define SM_VS (SM_KS + 2*AK*KS_STR)          // 13824
#define SM_PS (SM_VS + 2*AK*VS_STR)          // 23040
#define ATTN_SMEM ((SM_PS + AQ*PS_STR) * 4)  // 109568 B

__device__ __forceinline__ void attn_load_kv(float* sm, const float* __restrict__ qkv,
                                             int b, int h, int kt, int buf, int tid)
{
    const float* kbase = qkv + ((size_t)(b * TT + kt * AK)) * C3 + CC + h * HD;
    const float* vbase = kbase + CC;
    uint32_t kdst = smem_u32(sm + SM_KS + buf * AK * KS_STR);
    uint32_t vdst = smem_u32(sm + SM_VS + buf * AK * VS_STR);
#pragma unroll
    for (int i = 0; i < 8; i++) {
        int idx = tid + i * 128;
        int row = idx >> 4, c4 = idx & 15;
        CP_ASYNC16(kdst + (row * KS_STR + c4 * 4) * 4, kbase + (size_t)row * C3 + c4 * 4);
        CP_ASYNC16(vdst + (row * VS_STR + c4 * 4) * 4, vbase + (size_t)row * C3 + c4 * 4);
    }
}

__global__ __launch_bounds__(128, 2) void attn_tc(const float* __restrict__ qkv,
                                                  float* __restrict__ y)
{
    extern __shared__ float sm[];
    const int tid = threadIdx.x;
    const int wid = tid >> 5, lane = tid & 31;
    const int g = lane >> 2, t = lane & 3;
    const int qt = gridDim.x - 1 - blockIdx.x;   // longest blocks first
    const int h  = blockIdx.y;
    const int b  = blockIdx.z;
    const int q0 = qt * AQ;
    const int r0 = wid * 16 + g;

    // stage Q (global already permuted; copy verbatim, scale exact)
    {
        const float* qbase = qkv + ((size_t)(b * TT + q0)) * C3 + h * HD;
#pragma unroll
        for (int i = 0; i < 8; i++) {
            int idx = tid + i * 128;
            int row = idx >> 4, c4 = idx & 15;
            float4 v = *(const float4*)(qbase + (size_t)row * C3 + c4 * 4);
            v.x *= SCALE; v.y *= SCALE; v.z *= SCALE; v.w *= SCALE;
            *(float4*)(&sm[SM_QS + row * QS_STR + c4 * 4]) = v;
        }
    }
    attn_load_kv(sm, qkv, b, h, 0, 0, tid);
    CP_COMMIT();
    __syncthreads();

    // Q fragments: permuted layout -> (t,t+4) adjacent -> float2 loads
    uint32_t qf[8][4];
#pragma unroll
    for (int ds = 0; ds < 8; ds++) {
        float2 q0v = *(const float2*)(&sm[SM_QS + r0 * QS_STR + ds * 8 + 2 * t]);
        float2 q1v = *(const float2*)(&sm[SM_QS + (r0 + 8) * QS_STR + ds * 8 + 2 * t]);
        qf[ds][0] = __float_as_uint(q0v.x);   // k = t
        qf[ds][2] = __float_as_uint(q0v.y);   // k = t+4
        qf[ds][1] = __float_as_uint(q1v.x);
        qf[ds][3] = __float_as_uint(q1v.y);
    }

    float oacc[8][4];
#pragma unroll
    for (int nt = 0; nt < 8; nt++)
#pragma unroll
        for (int k = 0; k < 4; k++) oacc[nt][k] = 0.f;
    float mrow0 = -INFINITY, mrow1 = -INFINITY, lrow0 = 0.f, lrow1 = 0.f;

    for (int kt = 0; kt <= qt; kt++) {
        const int buf = kt & 1;
        CP_WAIT(0);
        __syncthreads();
        if (kt < qt) { attn_load_kv(sm, qkv, b, h, kt + 1, buf ^ 1, tid); CP_COMMIT(); }

        const float* ks = sm + SM_KS + buf * AK * KS_STR;
        const float* vs = sm + SM_VS + buf * AK * VS_STR;

        // S = Q K^T  (K fragments via LDS.64 on permuted layout)
        float sacc[8][4];
#pragma unroll
        for (int nt = 0; nt < 8; nt++)
#pragma unroll
            for (int k = 0; k < 4; k++) sacc[nt][k] = 0.f;
#pragma unroll
        for (int ds = 0; ds < 8; ds++) {
            uint32_t bf[8][2];
#pragma unroll
            for (int nt = 0; nt < 8; nt++) {
                float2 kv = *(const float2*)(&ks[(nt * 8 + g) * KS_STR + ds * 8 + 2 * t]);
                bf[nt][0] = __float_as_uint(kv.x);
                bf[nt][1] = __float_as_uint(kv.y);
            }
#pragma unroll
            for (int nt = 0; nt < 8; nt++)
                mma_tf32(sacc[nt], qf[ds], bf[nt]);
        }

        // causal mask (diagonal tile)
        if (kt == qt) {
#pragma unroll
            for (int nt = 0; nt < 8; nt++) {
                int c = nt * 8 + 2 * t;
                if (c     > r0)     sacc[nt][0] = -1e30f;
                if (c + 1 > r0)     sacc[nt][1] = -1e30f;
                if (c     > r0 + 8) sacc[nt][2] = -1e30f;
                if (c + 1 > r0 + 8) sacc[nt][3] = -1e30f;
            }
        }

        // online softmax
        float tm0 = -INFINITY, tm1 = -INFINITY;
#pragma unroll
        for (int nt = 0; nt < 8; nt++) {
            tm0 = fmaxf(tm0, fmaxf(sacc[nt][0], sacc[nt][1]));
            tm1 = fmaxf(tm1, fmaxf(sacc[nt][2], sacc[nt][3]));
        }
        tm0 = fmaxf(tm0, __shfl_xor_sync(0xffffffffu, tm0, 1));
        tm0 = fmaxf(tm0, __shfl_xor_sync(0xffffffffu, tm0, 2));
        tm1 = fmaxf(tm1, __shfl_xor_sync(0xffffffffu, tm1, 1));
        tm1 = fmaxf(tm1, __shfl_xor_sync(0xffffffffu, tm1, 2));
        float m0 = fmaxf(mrow0, tm0), m1 = fmaxf(mrow1, tm1);
        float a0 = __expf(mrow0 - m0), a1 = __expf(mrow1 - m1);
        mrow0 = m0; mrow1 = m1;
        float rs0 = 0.f, rs1 = 0.f;
#pragma unroll
        for (int nt = 0; nt < 8; nt++) {
            sacc[nt][0] = __expf(sacc[nt][0] - m0); rs0 += sacc[nt][0];
            sacc[nt][1] = __expf(sacc[nt][1] - m0); rs0 += sacc[nt][1];
            sacc[nt][2] = __expf(sacc[nt][2] - m1); rs1 += sacc[nt][2];
            sacc[nt][3] = __expf(sacc[nt][3] - m1); rs1 += sacc[nt][3];
        }
        rs0 += __shfl_xor_sync(0xffffffffu, rs0, 1);
        rs0 += __shfl_xor_sync(0xffffffffu, rs0, 2);
        rs1 += __shfl_xor_sync(0xffffffffu, rs1, 1);
        rs1 += __shfl_xor_sync(0xffffffffu, rs1, 2);
        lrow0 = lrow0 * a0 + rs0;
        lrow1 = lrow1 * a1 + rs1;
#pragma unroll
        for (int nt = 0; nt < 8; nt++) {
            oacc[nt][0] *= a0; oacc[nt][1] *= a0;
            oacc[nt][2] *= a1; oacc[nt][3] *= a1;
        }

        // stage P (tf32-rounded), natural col order
#pragma unroll
        for (int nt = 0; nt < 8; nt++) {
            float2 p0 = make_float2(rn_tf32(sacc[nt][0]), rn_tf32(sacc[nt][1]));
            float2 p1 = make_float2(rn_tf32(sacc[nt][2]), rn_tf32(sacc[nt][3]));
            *(float2*)(&sm[SM_PS + r0 * PS_STR + nt * 8 + 2 * t]) = p0;
            *(float2*)(&sm[SM_PS + (r0 + 8) * PS_STR + nt * 8 + 2 * t]) = p1;
        }
        __syncwarp();

        // O += P @ V
#pragma unroll
        for (int kk = 0; kk < 8; kk++) {
            uint32_t af[4];
            af[0] = __float_as_uint(sm[SM_PS + r0 * PS_STR + kk * 8 + t]);
            af[1] = __float_as_uint(sm[SM_PS + (r0 + 8) * PS_STR + kk * 8 + t]);
            af[2] = __float_as_uint(sm[SM_PS + r0 * PS_STR + kk * 8 + t + 4]);
            af[3] = __float_as_uint(sm[SM_PS + (r0 + 8) * PS_STR + kk * 8 + t + 4]);
            uint32_t bf[8][2];
#pragma unroll
            for (int nt = 0; nt < 8; nt++) {
                bf[nt][0] = __float_as_uint(vs[(kk * 8 + t) * VS_STR + nt * 8 + g]);
                bf[nt][1] = __float_as_uint(vs[(kk * 8 + t + 4) * VS_STR + nt * 8 + g]);
            }
#pragma unroll
            for (int nt = 0; nt < 8; nt++)
                mma_tf32(oacc[nt], af, bf[nt]);
        }
    }

    // normalize + store (tf32-rounded; natural order)
    float inv0 = 1.0f / lrow0, inv1 = 1.0f / lrow1;
    float* ybase = y + ((size_t)(b * TT + q0)) * CC + h * HD;
#pragma unroll
    for (int nt = 0; nt < 8; nt++) {
        float2 v0 = make_float2(rn_tf32(oacc[nt][0] * inv0), rn_tf32(oacc[nt][1] * inv0));
        float2 v1 = make_float2(rn_tf32(oacc[nt][2] * inv1), rn_tf32(oacc[nt][3] * inv1));
        *(float2*)(ybase + (size_t)r0 * CC + nt * 8 + 2 * t) = v0;
        *(float2*)(ybase + (size_t)(r0 + 8) * CC + nt * 8 + 2 * t) = v1;
    }
}

// ---------------------------------------------------------------- launch
extern "C" void kernel_launch(void* const* d_in, const int* in_sizes, int n_in,
                              void* d_out, int out_size)
{
    const float* x      = (const float*)d_in[0];
    const float* w_attn = (const float*)d_in[1];
    const float* b_attn = (const float*)d_in[2];
    const float* w_proj = (const float*)d_in[3];
    const float* b_proj = (const float*)d_in[4];
    float* out = (float*)d_out;

    float *qkv, *yb, *xr, *wa, *wp;
    cudaGetSymbolAddress((void**)&qkv, g_qkv);
    cudaGetSymbolAddress((void**)&yb,  g_y);
    cudaGetSymbolAddress((void**)&xr,  g_xr);
    cudaGetSymbolAddress((void**)&wa,  g_wa);
    cudaGetSymbolAddress((void**)&wp,  g_wp);

    cudaFuncSetAttribute(gemm_tf32, cudaFuncAttributeMaxDynamicSharedMemorySize, GEMM_SMEM);
    cudaFuncSetAttribute(attn_tc,   cudaFuncAttributeMaxDynamicSharedMemorySize, ATTN_SMEM);

    // 0) round operands to tf32
    round_tf32_kernel<<<(BT * CC) / 1024, 256>>>(x, xr);
    round_tf32_kernel<<<(CC * C3) / 1024, 256>>>(w_attn, wa);
    round_tf32_kernel<<<(CC * CC) / 1024, 256>>>(w_proj, wp);

    // 1) QKV = x @ w_attn + b_attn  (tf32; output rounded, Q/K cols permuted)
    gemm_tf32<<<dim3(C3 / GBN, BT / GBM), 256, GEMM_SMEM>>>(xr, wa, b_attn, qkv,
                                                            BT, C3, CC, 1, 1);

    // 2) causal attention
    attn_tc<<<dim3(TT / AQ, NH, BB), 128, ATTN_SMEM>>>(qkv, yb);

    // 3) out = y @ w_proj + b_proj  (tf32; fp32 output, no perm)
    gemm_tf32<<<dim3(CC / GBN, BT / GBM), 256, GEMM_SMEM>>>(yb, wp, b_proj, out,
                                                            BT, CC, CC, 0, 0);
}